// round 9
// baseline (speedup 1.0000x reference)
#include <cuda_runtime.h>

#define NB       4096        // batch (selection axis)
#define NT       256         // T
#define ND       64          // D
#define NCOL     (NT * ND)   // 16384 columns per tensor
#define KRANK    204         // int(0.05 * 4096), 0-based rank
#define G        16          // columns per block (4 float4 columns = 64 B/row)
#define CAPC     416         // flat candidate capacity per column (mean 301, sd 16.7)
#define NTHREADS 256
#define NWARP    8

__device__ float  g_var[2 * NCOL];
__device__ double g_pa[16];
__device__ double g_pr[16];

static __device__ __forceinline__ unsigned key_of(float f) {
    unsigned u = __float_as_uint(f);
    unsigned mask = (unsigned)((int)u >> 31) | 0x80000000u;
    return u ^ mask;  // monotone: key order == float ascending order
}
static __device__ __forceinline__ float float_of(unsigned k) {
    unsigned mask = (k & 0x80000000u) ? 0x80000000u : 0xFFFFFFFFu;
    return __uint_as_float(k ^ mask);
}

// find the 256-bin bucket containing 0-based rank k; k becomes rank-in-bucket.
// cc[i] = count of bin (lane*8 + i). Warp-collective.
static __device__ __forceinline__ unsigned find_bucket(const unsigned cc[8], int& kk, int lane) {
    unsigned lanesum = 0;
    #pragma unroll
    for (int i = 0; i < 8; i++) lanesum += cc[i];
    unsigned s = lanesum;
    #pragma unroll
    for (int off = 1; off < 32; off <<= 1) {
        unsigned n = __shfl_up_sync(0xffffffffu, s, off);
        if (lane >= off) s += n;
    }
    unsigned run = s - lanesum;  // exclusive prefix over lanes
    int bucket = -1, nk = 0;
    #pragma unroll
    for (int i = 0; i < 8; i++) {
        if (bucket < 0 && (unsigned)kk >= run && (unsigned)kk < run + cc[i]) {
            bucket = lane * 8 + i;
            nk = kk - (int)run;
        }
        run += cc[i];
    }
    unsigned bal = __ballot_sync(0xffffffffu, bucket >= 0);
    int srcl = __ffs(bal) - 1;
    int bb = __shfl_sync(0xffffffffu, bucket, srcl);
    kk = __shfl_sync(0xffffffffu, nk, srcl);
    return (unsigned)bb;
}

__global__ void __launch_bounds__(NTHREADS, 6)
select_kernel(const float* __restrict__ xf, const float* __restrict__ xr) {
    extern __shared__ unsigned smem[];
    unsigned*       seg  = smem;                              // [G][CAPC]
    unsigned*       scnt = smem + G * CAPC;                   // [G]
    unsigned short* hist = (unsigned short*)(smem + G * CAPC + G);  // [NWARP][256] u16

    const int tid  = threadIdx.x;
    const int lane = tid & 31;
    const int w    = tid >> 5;

    const int bid    = blockIdx.x;               // 2048 blocks
    const int tensor = bid >> 10;
    const int rem    = bid & 1023;
    const int t      = rem >> 2;
    const int dgrp   = rem & 3;                  // which group of 16 columns

    const float* src = tensor ? xr : xf;
    const int c = tid & 3;                       // this thread's float4-column (0..3)
    const float4* p = reinterpret_cast<const float4*>(src) + (t * 16 + dgrp * 4 + c);
    const float THR = -1.45f;

    if (tid < G) scnt[tid] = 0;
    __syncthreads();

    // per-(thread,jj) shared addresses, hoisted out of the hot loop
    unsigned scnt_sa[4], seg_sa[4];
    #pragma unroll
    for (int jj = 0; jj < 4; jj++) {
        int col = c * 4 + jj;
        scnt_sa[jj] = (unsigned)__cvta_generic_to_shared(&scnt[col]);
        seg_sa[jj]  = (unsigned)__cvta_generic_to_shared(&seg[col * CAPC]);
    }

    // ---- streaming load + branchless predicated candidate capture ----
    // No C++ if{} in the hot path: pure @p/@q predication, zero BSSY/BSYNC.
    // Candidates are all negative floats, for which key_of(v) == ~bits(v).
    #pragma unroll 1
    for (int it = 0; it < 64; it += 4) {
        float4 buf[4];
        #pragma unroll
        for (int u = 0; u < 4; u++) {
            int r = (it + u) * 64 + (tid >> 2);
            buf[u] = __ldg(p + (size_t)r * (NCOL / 4));
        }
        #pragma unroll
        for (int u = 0; u < 4; u++) {
            float vv[4] = {buf[u].x, buf[u].y, buf[u].z, buf[u].w};
            #pragma unroll
            for (int jj = 0; jj < 4; jj++) {
                float v = vv[jj];
                asm volatile(
                    "{\n\t"
                    ".reg .pred p, q;\n\t"
                    ".reg .b32 s, k, a;\n\t"
                    "setp.lt.f32 p, %0, %1;\n\t"
                    "@p atom.shared.add.u32 s, [%2], 1;\n\t"
                    "setp.lt.and.u32 q, s, %3, p;\n\t"
                    "@q not.b32 k, %4;\n\t"
                    "@q mad.lo.u32 a, s, 4, %5;\n\t"
                    "@q st.shared.b32 [a], k;\n\t"
                    "}\n\t"
                    :: "f"(v), "f"(THR), "r"(scnt_sa[jj]),
                       "n"(CAPC), "r"(__float_as_uint(v)), "r"(seg_sa[jj])
                    : "memory");
            }
        }
    }
    __syncthreads();

    // ---- select: warp w owns columns w and w+8, flat candidate arrays ----
    unsigned short* h   = hist + w * 256;
    unsigned*       h32 = (unsigned*)h;          // for zeroing (128 words)
    const unsigned  lmlt = (1u << lane) - 1u;

    for (int cc2 = 0; cc2 < 2; cc2++) {
        const int col = w + cc2 * NWARP;
        unsigned* colb = seg + col * CAPC;
        const int cnt0 = (int)scnt[col];

        unsigned prefix = 0;
        int k = KRANK;

        if (cnt0 > KRANK && cnt0 <= CAPC) {
            int cntf = cnt0;
            for (int shift = 24; shift >= 0; shift -= 8) {
                #pragma unroll
                for (int i = 0; i < 4; i++) h32[i * 32 + lane] = 0;
                __syncwarp();
                for (int i0 = 0; i0 < cntf; i0 += 32) {
                    int i = i0 + lane;
                    bool a = i < cntf;
                    unsigned key = a ? colb[i] : 0u;
                    unsigned m = __ballot_sync(0xffffffffu, a);
                    if (a) {
                        unsigned bin = (key >> shift) & 255u;
                        unsigned peers = __match_any_sync(m, bin);
                        if (lane == __ffs(peers) - 1)
                            h[bin] = (unsigned short)(h[bin] + __popc(peers));
                    }
                }
                __syncwarp();
                unsigned c8[8];
                #pragma unroll
                for (int i = 0; i < 8; i++) c8[i] = h[lane * 8 + i];
                unsigned bucket = find_bucket(c8, k, lane);
                prefix |= bucket << shift;
                if (shift > 0) {
                    // in-place compaction; writes never pass the read frontier
                    int np = 0;
                    for (int i0 = 0; i0 < cntf; i0 += 32) {
                        int i = i0 + lane;
                        bool a = i < cntf;
                        unsigned key = a ? colb[i] : 0u;
                        bool ok = a && (((key >> shift) & 255u) == bucket);
                        unsigned m = __ballot_sync(0xffffffffu, ok);
                        if (ok) colb[np + __popc(m & lmlt)] = key;
                        np += __popc(m);
                    }
                    cntf = np;
                }
            }
        } else {
            // exact fallback (astronomically rare): 4-pass radix re-reading global
            const int cglob = t * 64 + dgrp * 16 + col;
            for (int shift = 24; shift >= 0; shift -= 8) {
                #pragma unroll
                for (int i = 0; i < 4; i++) h32[i * 32 + lane] = 0;
                __syncwarp();
                for (int i = lane; i < NB; i += 32) {
                    unsigned key = key_of(__ldg(src + (size_t)i * NCOL + cglob));
                    bool act = (shift == 24) ||
                               ((key >> (shift + 8)) == (prefix >> (shift + 8)));
                    unsigned m = __ballot_sync(0xffffffffu, act);
                    if (act) {
                        unsigned bin = (key >> shift) & 255u;
                        unsigned peers = __match_any_sync(m, bin);
                        if (lane == __ffs(peers) - 1)
                            h[bin] = (unsigned short)(h[bin] + __popc(peers));
                    }
                }
                __syncwarp();
                unsigned c8[8];
                #pragma unroll
                for (int i = 0; i < 8; i++) c8[i] = h[lane * 8 + i];
                unsigned bucket = find_bucket(c8, k, lane);
                prefix |= bucket << shift;
            }
        }

        if (lane == 0)
            g_var[tensor * NCOL + t * ND + dgrp * G + col] = float_of(prefix);
    }
}

// 16 blocks x 1024 threads: deterministic partial sums into fixed slots
__global__ void reduce_part(void) {
    const int tid  = threadIdx.x;
    const int lane = tid & 31;
    const int wid  = tid >> 5;
    const int i    = blockIdx.x * 1024 + tid;

    float vf = g_var[i];
    float vr = g_var[NCOL + i];
    float d  = fabsf(vf - vr);
    double a = (double)d;
    double r = (double)(d / (fabsf(vr) + 1e-8f));

    #pragma unroll
    for (int off = 16; off > 0; off >>= 1) {
        a += __shfl_down_sync(0xffffffffu, a, off);
        r += __shfl_down_sync(0xffffffffu, r, off);
    }
    __shared__ double sa[32], sr[32];
    if (lane == 0) { sa[wid] = a; sr[wid] = r; }
    __syncthreads();
    if (tid < 32) {
        a = sa[tid]; r = sr[tid];
        #pragma unroll
        for (int off = 16; off > 0; off >>= 1) {
            a += __shfl_down_sync(0xffffffffu, a, off);
            r += __shfl_down_sync(0xffffffffu, r, off);
        }
        if (tid == 0) { g_pa[blockIdx.x] = a; g_pr[blockIdx.x] = r; }
    }
}

// single thread: fixed-order final sum -> bitwise deterministic
__global__ void finalize_kernel(float* __restrict__ out) {
    double a = 0.0, r = 0.0;
    #pragma unroll
    for (int i = 0; i < 16; i++) { a += g_pa[i]; r += g_pr[i]; }
    out[0] = (float)(a / (double)NCOL);
    out[1] = (float)(r / (double)NCOL);
}

extern "C" void kernel_launch(void* const* d_in, const int* in_sizes, int n_in,
                              void* d_out, int out_size) {
    const float* xf = (const float*)d_in[0];
    const float* xr = (const float*)d_in[1];
    const int smem_bytes = (G * CAPC + G) * 4 + NWARP * 256 * 2;  // 30784
    cudaFuncSetAttribute(select_kernel,
                         cudaFuncAttributeMaxDynamicSharedMemorySize, smem_bytes);
    select_kernel<<<2 * NT * (ND / G), NTHREADS, smem_bytes>>>(xf, xr);
    reduce_part<<<16, 1024>>>();
    finalize_kernel<<<1, 1>>>((float*)d_out);
}

// round 10
// speedup vs baseline: 1.5081x; 1.5081x over previous
#include <cuda_runtime.h>

#define NB       4096        // batch (selection axis)
#define NT       256         // T
#define ND       64          // D
#define NCOL     (NT * ND)   // 16384 columns per tensor
#define KRANK    204         // int(0.05 * 4096), 0-based rank
#define G        16          // columns per block (4 float4 columns = 64 B/row)
#define CAPC     416         // candidate capacity per column (mean 301, sd 16.7)
#define CAPC1    (CAPC + 1)  // +1 garbage slot for branch-free stores
#define NTHREADS 256
#define NWARP    8

// key_of(-1.45f): bits(-1.45f)=0xBFB9999A, key=~bits for negatives
#define THRKEY   0x40466665u
#define BASEKEY  (THRKEY - (1u << 22))   // 256 bins of 2^14 keys each

__device__ float  g_var[2 * NCOL];
__device__ double g_pa[16];
__device__ double g_pr[16];

static __device__ __forceinline__ unsigned key_of(float f) {
    unsigned u = __float_as_uint(f);
    unsigned mask = (unsigned)((int)u >> 31) | 0x80000000u;
    return u ^ mask;  // monotone: key order == float ascending order
}
static __device__ __forceinline__ float float_of(unsigned k) {
    unsigned mask = (k & 0x80000000u) ? 0x80000000u : 0xFFFFFFFFu;
    return __uint_as_float(k ^ mask);
}
// linear bin over candidate key range; bin 0 = underflow tail (exact via
// survivor byte-select), bin 255 merges the top two widths. Always in [0,255].
static __device__ __forceinline__ int linbin(unsigned key) {
    int d = (int)(key - BASEKEY);
    int b = (d >> 14) + 1;
    b = b < 0 ? 0 : b;
    return b > 255 ? 255 : b;
}

// find the 256-bin bucket containing 0-based rank k; k becomes rank-in-bucket.
// cc[i] = count of bin (lane*8 + i). Warp-collective.
static __device__ __forceinline__ unsigned find_bucket(const unsigned cc[8], int& kk, int lane) {
    unsigned lanesum = 0;
    #pragma unroll
    for (int i = 0; i < 8; i++) lanesum += cc[i];
    unsigned s = lanesum;
    #pragma unroll
    for (int off = 1; off < 32; off <<= 1) {
        unsigned n = __shfl_up_sync(0xffffffffu, s, off);
        if (lane >= off) s += n;
    }
    unsigned run = s - lanesum;  // exclusive prefix over lanes
    int bucket = -1, nk = 0;
    #pragma unroll
    for (int i = 0; i < 8; i++) {
        if (bucket < 0 && (unsigned)kk >= run && (unsigned)kk < run + cc[i]) {
            bucket = lane * 8 + i;
            nk = kk - (int)run;
        }
        run += cc[i];
    }
    unsigned bal = __ballot_sync(0xffffffffu, bucket >= 0);
    int srcl = __ffs(bal) - 1;
    int bb = __shfl_sync(0xffffffffu, bucket, srcl);
    kk = __shfl_sync(0xffffffffu, nk, srcl);
    return (unsigned)bb;
}

__global__ void __launch_bounds__(NTHREADS, 6)
select_kernel(const float* __restrict__ xf, const float* __restrict__ xr) {
    extern __shared__ unsigned smem[];
    unsigned* seg  = smem;                        // [G][CAPC1]
    unsigned* scnt = smem + G * CAPC1;            // [G]
    unsigned* hist = scnt + G;                    // [NWARP][256] u32

    const int tid  = threadIdx.x;
    const int lane = tid & 31;
    const int w    = tid >> 5;

    const int bid    = blockIdx.x;                // 2048 blocks
    const int tensor = bid >> 10;
    const int rem    = bid & 1023;
    const int t      = rem >> 2;
    const int dgrp   = rem & 3;                   // which group of 16 columns

    const float* src = tensor ? xr : xf;
    const int c = tid & 3;                        // this thread's float4-column (0..3)
    const float4* p = reinterpret_cast<const float4*>(src) + (t * 16 + dgrp * 4 + c);
    const float THR = -1.45f;

    if (tid < G) scnt[tid] = 0;
    __syncthreads();

    // hoisted per-(thread,jj) pointers
    unsigned* cntp[4];
    unsigned* segp[4];
    #pragma unroll
    for (int jj = 0; jj < 4; jj++) {
        int col = c * 4 + jj;
        cntp[jj] = &scnt[col];
        segp[jj] = &seg[col * CAPC1];
    }

    // ---- streaming load + BRANCH-FREE candidate capture ----
    // Every element: unconditional atomicAdd (adds 0/1) + unconditional store
    // (non-candidates land in the write-only garbage slot CAPC). No BSSY/BSYNC,
    // no asm fences: ptxas pipelines the 16 independent ATOMS/STS chains and
    // keeps hoisting the next iteration's LDGs.
    #pragma unroll 1
    for (int it = 0; it < 64; it += 4) {
        float4 buf[4];
        #pragma unroll
        for (int u = 0; u < 4; u++) {
            int r = (it + u) * 64 + (tid >> 2);
            buf[u] = __ldg(p + (size_t)r * (NCOL / 4));
        }
        #pragma unroll
        for (int u = 0; u < 4; u++) {
            float vv[4] = {buf[u].x, buf[u].y, buf[u].z, buf[u].w};
            #pragma unroll
            for (int jj = 0; jj < 4; jj++) {
                float v = vv[jj];
                bool pred = v < THR;
                unsigned slot = atomicAdd(cntp[jj], (unsigned)pred);
                unsigned idx = (pred && slot < CAPC) ? slot : CAPC;
                segp[jj][idx] = ~__float_as_uint(v);  // key (valid for negatives)
            }
        }
    }
    __syncthreads();

    // ---- select: warp w owns columns w and w+8 ----
    unsigned* h32 = hist + w * 256;
    const unsigned lmlt = (1u << lane) - 1u;

    for (int cc2 = 0; cc2 < 2; cc2++) {
        const int col = w + cc2 * NWARP;
        unsigned* colb = seg + col * CAPC1;
        const int cnt0 = (int)scnt[col];

        unsigned prefix = 0;
        int k = KRANK;

        if (cnt0 > KRANK && cnt0 <= CAPC) {
            // ---- pass L: linear-bin histogram over all candidates ----
            #pragma unroll
            for (int i = 0; i < 8; i++) h32[i * 32 + lane] = 0;
            __syncwarp();
            for (int i0 = 0; i0 < cnt0; i0 += 32) {
                int i = i0 + lane;
                if (i < cnt0) atomicAdd(&h32[linbin(colb[i])], 1u);
            }
            __syncwarp();
            unsigned c8[8];
            #pragma unroll
            for (int i = 0; i < 8; i++) c8[i] = h32[lane * 8 + i];
            int lb = (int)find_bucket(c8, k, lane);

            // compact survivors (linbin == lb) to front
            int cntf = 0;
            for (int i0 = 0; i0 < cnt0; i0 += 32) {
                int i = i0 + lane;
                bool a = i < cnt0;
                unsigned key = a ? colb[i] : 0u;
                bool ok = a && (linbin(key) == lb);
                unsigned m = __ballot_sync(0xffffffffu, ok);
                if (ok) colb[cntf + __popc(m & lmlt)] = key;
                cntf += __popc(m);
            }

            // ---- exact byte-select over the (few) survivors ----
            for (int shift = 24; shift >= 0; shift -= 8) {
                #pragma unroll
                for (int i = 0; i < 8; i++) h32[i * 32 + lane] = 0;
                __syncwarp();
                for (int i0 = 0; i0 < cntf; i0 += 32) {
                    int i = i0 + lane;
                    if (i < cntf) atomicAdd(&h32[(colb[i] >> shift) & 255u], 1u);
                }
                __syncwarp();
                #pragma unroll
                for (int i = 0; i < 8; i++) c8[i] = h32[lane * 8 + i];
                unsigned bucket = find_bucket(c8, k, lane);
                prefix |= bucket << shift;
                if (shift > 0) {
                    int np = 0;
                    for (int i0 = 0; i0 < cntf; i0 += 32) {
                        int i = i0 + lane;
                        bool a = i < cntf;
                        unsigned key = a ? colb[i] : 0u;
                        bool ok = a && (((key >> shift) & 255u) == bucket);
                        unsigned m = __ballot_sync(0xffffffffu, ok);
                        if (ok) colb[np + __popc(m & lmlt)] = key;
                        np += __popc(m);
                    }
                    cntf = np;
                }
            }
        } else {
            // exact fallback (astronomically rare): 4-pass radix re-reading global
            const int cglob = t * 64 + dgrp * 16 + col;
            for (int shift = 24; shift >= 0; shift -= 8) {
                #pragma unroll
                for (int i = 0; i < 8; i++) h32[i * 32 + lane] = 0;
                __syncwarp();
                for (int i = lane; i < NB; i += 32) {
                    unsigned key = key_of(__ldg(src + (size_t)i * NCOL + cglob));
                    bool act = (shift == 24) ||
                               ((key >> (shift + 8)) == (prefix >> (shift + 8)));
                    if (act) atomicAdd(&h32[(key >> shift) & 255u], 1u);
                }
                __syncwarp();
                unsigned c8[8];
                #pragma unroll
                for (int i = 0; i < 8; i++) c8[i] = h32[lane * 8 + i];
                unsigned bucket = find_bucket(c8, k, lane);
                prefix |= bucket << shift;
            }
        }

        if (lane == 0)
            g_var[tensor * NCOL + t * ND + dgrp * G + col] = float_of(prefix);
    }
}

// 16 blocks x 1024 threads: deterministic partial sums into fixed slots
__global__ void reduce_part(void) {
    const int tid  = threadIdx.x;
    const int lane = tid & 31;
    const int wid  = tid >> 5;
    const int i    = blockIdx.x * 1024 + tid;

    float vf = g_var[i];
    float vr = g_var[NCOL + i];
    float d  = fabsf(vf - vr);
    double a = (double)d;
    double r = (double)(d / (fabsf(vr) + 1e-8f));

    #pragma unroll
    for (int off = 16; off > 0; off >>= 1) {
        a += __shfl_down_sync(0xffffffffu, a, off);
        r += __shfl_down_sync(0xffffffffu, r, off);
    }
    __shared__ double sa[32], sr[32];
    if (lane == 0) { sa[wid] = a; sr[wid] = r; }
    __syncthreads();
    if (tid < 32) {
        a = sa[tid]; r = sr[tid];
        #pragma unroll
        for (int off = 16; off > 0; off >>= 1) {
            a += __shfl_down_sync(0xffffffffu, a, off);
            r += __shfl_down_sync(0xffffffffu, r, off);
        }
        if (tid == 0) { g_pa[blockIdx.x] = a; g_pr[blockIdx.x] = r; }
    }
}

// single thread: fixed-order final sum -> bitwise deterministic
__global__ void finalize_kernel(float* __restrict__ out) {
    double a = 0.0, r = 0.0;
    #pragma unroll
    for (int i = 0; i < 16; i++) { a += g_pa[i]; r += g_pr[i]; }
    out[0] = (float)(a / (double)NCOL);
    out[1] = (float)(r / (double)NCOL);
}

extern "C" void kernel_launch(void* const* d_in, const int* in_sizes, int n_in,
                              void* d_out, int out_size) {
    const float* xf = (const float*)d_in[0];
    const float* xr = (const float*)d_in[1];
    const int smem_bytes = (G * CAPC1 + G + NWARP * 256) * 4;  // 34944
    cudaFuncSetAttribute(select_kernel,
                         cudaFuncAttributeMaxDynamicSharedMemorySize, smem_bytes);
    select_kernel<<<2 * NT * (ND / G), NTHREADS, smem_bytes>>>(xf, xr);
    reduce_part<<<16, 1024>>>();
    finalize_kernel<<<1, 1>>>((float*)d_out);
}

// round 11
// speedup vs baseline: 1.5505x; 1.0281x over previous
#include <cuda_runtime.h>

#define NB       4096        // batch (selection axis)
#define NT       256         // T
#define ND       64          // D
#define NCOL     (NT * ND)   // 16384 columns per tensor
#define KRANK    204         // int(0.05 * 4096), 0-based rank
#define G        16          // columns per block (4 float4 columns = 64 B/row)
#define CAP      79          // per-(column,warp) segment capacity (mu 37.6, sd 5.9)
#define CAP1     (CAP + 1)   // +1 garbage slot for branch-free stores
#define NTHREADS 256
#define NWARP    8

// key_of(-1.45f): bits(-1.45f)=0xBFB9999A, key=~bits for negatives
#define THRKEY   0x40466665u
#define BASEKEY  (THRKEY - (1u << 22))   // 256 linear bins of 2^14 keys each

__device__ float  g_var[2 * NCOL];
__device__ double g_pa[16];
__device__ double g_pr[16];

static __device__ __forceinline__ unsigned key_of(float f) {
    unsigned u = __float_as_uint(f);
    unsigned mask = (unsigned)((int)u >> 31) | 0x80000000u;
    return u ^ mask;  // monotone: key order == float ascending order
}
static __device__ __forceinline__ float float_of(unsigned k) {
    unsigned mask = (k & 0x80000000u) ? 0x80000000u : 0xFFFFFFFFu;
    return __uint_as_float(k ^ mask);
}
// linear bin over the candidate key range; bin 0 = underflow tail.
static __device__ __forceinline__ int linbin(unsigned key) {
    int d = (int)(key - BASEKEY);
    int b = (d >> 14) + 1;
    b = b < 0 ? 0 : b;
    return b > 255 ? 255 : b;
}

// find the 256-bin bucket containing 0-based rank k; k becomes rank-in-bucket.
static __device__ __forceinline__ unsigned find_bucket(const unsigned cc[8], int& kk, int lane) {
    unsigned lanesum = 0;
    #pragma unroll
    for (int i = 0; i < 8; i++) lanesum += cc[i];
    unsigned s = lanesum;
    #pragma unroll
    for (int off = 1; off < 32; off <<= 1) {
        unsigned n = __shfl_up_sync(0xffffffffu, s, off);
        if (lane >= off) s += n;
    }
    unsigned run = s - lanesum;  // exclusive prefix over lanes
    int bucket = -1, nk = 0;
    #pragma unroll
    for (int i = 0; i < 8; i++) {
        if (bucket < 0 && (unsigned)kk >= run && (unsigned)kk < run + cc[i]) {
            bucket = lane * 8 + i;
            nk = kk - (int)run;
        }
        run += cc[i];
    }
    unsigned bal = __ballot_sync(0xffffffffu, bucket >= 0);
    int srcl = __ffs(bal) - 1;
    int bb = __shfl_sync(0xffffffffu, bucket, srcl);
    kk = __shfl_sync(0xffffffffu, nk, srcl);
    return (unsigned)bb;
}

__global__ void __launch_bounds__(NTHREADS, 5)
select_kernel(const float* __restrict__ xf, const float* __restrict__ xr) {
    extern __shared__ unsigned smem[];
    unsigned*       seg  = smem;                            // [G][NWARP][CAP1]
    unsigned*       cnt  = smem + G * NWARP * CAP1;         // [G][NWARP]
    unsigned short* hist = (unsigned short*)(cnt + G * NWARP);  // [NWARP][256] u16

    const int tid  = threadIdx.x;
    const int lane = tid & 31;
    const int w    = tid >> 5;

    const int bid    = blockIdx.x;               // 2048 blocks
    const int tensor = bid >> 10;
    const int rem    = bid & 1023;
    const int t      = rem >> 2;
    const int dgrp   = rem & 3;                  // which group of 16 columns

    const float* src = tensor ? xr : xf;
    const int c = tid & 3;                       // this thread's float4-column (0..3)
    const float4* p = reinterpret_cast<const float4*>(src) + (t * 16 + dgrp * 4 + c);
    const float THR = -1.45f;

    const unsigned grpmask = 0x11111111u << c;   // the 8 lanes sharing this c
    const unsigned lmlt    = (1u << lane) - 1u;

    // hoisted per-(thread,jj) segment bases
    unsigned* segp[4];
    #pragma unroll
    for (int jj = 0; jj < 4; jj++)
        segp[jj] = &seg[((c * 4 + jj) * NWARP + w) * CAP1];

    unsigned wcnt[4] = {0, 0, 0, 0};   // running counts (uniform within c-subgroup)

    // ---- streaming load + ATOMICS-FREE, BRANCH-FREE candidate capture ----
    // Slot assignment via ballot prefix on per-warp register counters: no ATOMS,
    // no long-latency dependency, unconditional store (garbage slot CAP).
    #pragma unroll 1
    for (int it = 0; it < 64; it += 4) {
        float4 buf[4];
        #pragma unroll
        for (int u = 0; u < 4; u++) {
            int r = (it + u) * 64 + (tid >> 2);
            buf[u] = __ldg(p + (size_t)r * (NCOL / 4));
        }
        #pragma unroll
        for (int u = 0; u < 4; u++) {
            float vv[4] = {buf[u].x, buf[u].y, buf[u].z, buf[u].w};
            #pragma unroll
            for (int jj = 0; jj < 4; jj++) {
                float v = vv[jj];
                bool pred = v < THR;
                unsigned bal = __ballot_sync(0xffffffffu, pred);
                unsigned mc  = bal & grpmask;
                unsigned slot = wcnt[jj] + __popc(mc & lmlt);
                unsigned idx = (pred && slot < CAP) ? slot : CAP;
                segp[jj][idx] = ~__float_as_uint(v);   // key (negatives: key==~bits)
                wcnt[jj] += __popc(mc);
            }
        }
    }
    if (lane < 4) {  // lane l is in subgroup c==l; counts uniform in subgroup
        #pragma unroll
        for (int jj = 0; jj < 4; jj++)
            cnt[(lane * 4 + jj) * NWARP + w] = wcnt[jj];
    }
    __syncthreads();

    // ---- select: warp w owns columns w and w+8 ----
    unsigned short* h   = hist + w * 256;
    unsigned*       h32 = (unsigned*)h;          // for zeroing (128 words)

    for (int cc2 = 0; cc2 < 2; cc2++) {
        const int col = w + cc2 * NWARP;
        unsigned* colb = seg + col * NWARP * CAP1;   // flat base (segment 0)

        int total = 0;
        bool ovf = false;
        int cs_arr[NWARP];
        #pragma unroll
        for (int s = 0; s < NWARP; s++) {
            int cs = (int)cnt[col * NWARP + s];
            if (cs > CAP) ovf = true;
            cs_arr[s] = cs;
            total += cs;
        }

        unsigned prefix = 0;
        int k = KRANK;

        if (!ovf && total > KRANK) {
            // ---- pass L: segmented linbin histogram ----
            #pragma unroll
            for (int i = 0; i < 4; i++) h32[i * 32 + lane] = 0;
            __syncwarp();
            for (int s = 0; s < NWARP; s++) {
                int cs = cs_arr[s];
                for (int i0 = 0; i0 < cs; i0 += 32) {
                    int i = i0 + lane;
                    bool a = i < cs;
                    unsigned key = a ? colb[s * CAP1 + i] : 0u;
                    unsigned m = __ballot_sync(0xffffffffu, a);
                    if (a) {
                        unsigned bin = (unsigned)linbin(key);
                        unsigned peers = __match_any_sync(m, bin);
                        if (lane == __ffs(peers) - 1)
                            h[bin] = (unsigned short)(h[bin] + __popc(peers));
                    }
                }
            }
            __syncwarp();
            unsigned c8[8];
            #pragma unroll
            for (int i = 0; i < 8; i++) c8[i] = h[lane * 8 + i];
            int lb = (int)find_bucket(c8, k, lane);

            // compact survivors (linbin == lb) from segments to flat front
            // (write pos <= elements-read so writes never pass the read frontier)
            int cntf = 0;
            for (int s = 0; s < NWARP; s++) {
                int cs = cs_arr[s];
                for (int i0 = 0; i0 < cs; i0 += 32) {
                    int i = i0 + lane;
                    bool a = i < cs;
                    unsigned key = a ? colb[s * CAP1 + i] : 0u;
                    bool ok = a && (linbin(key) == lb);
                    unsigned m = __ballot_sync(0xffffffffu, ok);
                    if (ok) colb[cntf + __popc(m & lmlt)] = key;
                    cntf += __popc(m);
                }
            }

            // ---- exact byte-select over the (few) survivors ----
            for (int shift = 24; shift >= 0; shift -= 8) {
                #pragma unroll
                for (int i = 0; i < 4; i++) h32[i * 32 + lane] = 0;
                __syncwarp();
                for (int i0 = 0; i0 < cntf; i0 += 32) {
                    int i = i0 + lane;
                    bool a = i < cntf;
                    unsigned key = a ? colb[i] : 0u;
                    unsigned m = __ballot_sync(0xffffffffu, a);
                    if (a) {
                        unsigned bin = (key >> shift) & 255u;
                        unsigned peers = __match_any_sync(m, bin);
                        if (lane == __ffs(peers) - 1)
                            h[bin] = (unsigned short)(h[bin] + __popc(peers));
                    }
                }
                __syncwarp();
                #pragma unroll
                for (int i = 0; i < 8; i++) c8[i] = h[lane * 8 + i];
                unsigned bucket = find_bucket(c8, k, lane);
                prefix |= bucket << shift;
                if (shift > 0) {
                    int np = 0;
                    for (int i0 = 0; i0 < cntf; i0 += 32) {
                        int i = i0 + lane;
                        bool a = i < cntf;
                        unsigned key = a ? colb[i] : 0u;
                        bool ok = a && (((key >> shift) & 255u) == bucket);
                        unsigned m = __ballot_sync(0xffffffffu, ok);
                        if (ok) colb[np + __popc(m & lmlt)] = key;
                        np += __popc(m);
                    }
                    cntf = np;
                }
            }
        } else {
            // exact fallback (rare): 4-pass radix select re-reading global
            const int cglob = t * 64 + dgrp * 16 + col;
            for (int shift = 24; shift >= 0; shift -= 8) {
                #pragma unroll
                for (int i = 0; i < 4; i++) h32[i * 32 + lane] = 0;
                __syncwarp();
                for (int i = lane; i < NB; i += 32) {
                    unsigned key = key_of(__ldg(src + (size_t)i * NCOL + cglob));
                    bool act = (shift == 24) ||
                               ((key >> (shift + 8)) == (prefix >> (shift + 8)));
                    unsigned m = __ballot_sync(0xffffffffu, act);
                    if (act) {
                        unsigned bin = (key >> shift) & 255u;
                        unsigned peers = __match_any_sync(m, bin);
                        if (lane == __ffs(peers) - 1)
                            h[bin] = (unsigned short)(h[bin] + __popc(peers));
                    }
                }
                __syncwarp();
                unsigned c8[8];
                #pragma unroll
                for (int i = 0; i < 8; i++) c8[i] = h[lane * 8 + i];
                unsigned bucket = find_bucket(c8, k, lane);
                prefix |= bucket << shift;
            }
        }

        if (lane == 0)
            g_var[tensor * NCOL + t * ND + dgrp * G + col] = float_of(prefix);
    }
}

// 16 blocks x 1024 threads: deterministic partial sums into fixed slots
__global__ void reduce_part(void) {
    const int tid  = threadIdx.x;
    const int lane = tid & 31;
    const int wid  = tid >> 5;
    const int i    = blockIdx.x * 1024 + tid;

    float vf = g_var[i];
    float vr = g_var[NCOL + i];
    float d  = fabsf(vf - vr);
    double a = (double)d;
    double r = (double)(d / (fabsf(vr) + 1e-8f));

    #pragma unroll
    for (int off = 16; off > 0; off >>= 1) {
        a += __shfl_down_sync(0xffffffffu, a, off);
        r += __shfl_down_sync(0xffffffffu, r, off);
    }
    __shared__ double sa[32], sr[32];
    if (lane == 0) { sa[wid] = a; sr[wid] = r; }
    __syncthreads();
    if (tid < 32) {
        a = sa[tid]; r = sr[tid];
        #pragma unroll
        for (int off = 16; off > 0; off >>= 1) {
            a += __shfl_down_sync(0xffffffffu, a, off);
            r += __shfl_down_sync(0xffffffffu, r, off);
        }
        if (tid == 0) { g_pa[blockIdx.x] = a; g_pr[blockIdx.x] = r; }
    }
}

// single thread: fixed-order final sum -> bitwise deterministic
__global__ void finalize_kernel(float* __restrict__ out) {
    double a = 0.0, r = 0.0;
    #pragma unroll
    for (int i = 0; i < 16; i++) { a += g_pa[i]; r += g_pr[i]; }
    out[0] = (float)(a / (double)NCOL);
    out[1] = (float)(r / (double)NCOL);
}

extern "C" void kernel_launch(void* const* d_in, const int* in_sizes, int n_in,
                              void* d_out, int out_size) {
    const float* xf = (const float*)d_in[0];
    const float* xr = (const float*)d_in[1];
    const int smem_bytes = (G * NWARP * CAP1 + G * NWARP) * 4 + NWARP * 256 * 2;  // 45568
    cudaFuncSetAttribute(select_kernel,
                         cudaFuncAttributeMaxDynamicSharedMemorySize, smem_bytes);
    select_kernel<<<2 * NT * (ND / G), NTHREADS, smem_bytes>>>(xf, xr);
    reduce_part<<<16, 1024>>>();
    finalize_kernel<<<1, 1>>>((float*)d_out);
}

// round 12
// speedup vs baseline: 2.0988x; 1.3536x over previous
#include <cuda_runtime.h>

#define NB       4096        // batch (selection axis)
#define NT       256         // T
#define ND       64          // D
#define NCOL     (NT * ND)   // 16384 columns per tensor
#define KRANK    204         // int(0.05 * 4096), 0-based rank
#define G        16          // columns per block (4 float4 columns = 64 B/row)
#define CAPC     416         // candidate capacity per column (mean 301, sd 16.7)
#define NTHREADS 256
#define NWARP    8

__device__ float  g_var[2 * NCOL];
__device__ double g_pa[16];
__device__ double g_pr[16];

static __device__ __forceinline__ unsigned key_of(float f) {
    unsigned u = __float_as_uint(f);
    unsigned mask = (unsigned)((int)u >> 31) | 0x80000000u;
    return u ^ mask;  // monotone: key order == float ascending order
}
static __device__ __forceinline__ float float_of(unsigned k) {
    unsigned mask = (k & 0x80000000u) ? 0x80000000u : 0xFFFFFFFFu;
    return __uint_as_float(k ^ mask);
}

// find the 256-bin bucket containing 0-based rank k; k becomes rank-in-bucket.
// cc[i] = count of bin (lane*8 + i). Warp-collective.
static __device__ __forceinline__ unsigned find_bucket(const unsigned cc[8], int& kk, int lane) {
    unsigned lanesum = 0;
    #pragma unroll
    for (int i = 0; i < 8; i++) lanesum += cc[i];
    unsigned s = lanesum;
    #pragma unroll
    for (int off = 1; off < 32; off <<= 1) {
        unsigned n = __shfl_up_sync(0xffffffffu, s, off);
        if (lane >= off) s += n;
    }
    unsigned run = s - lanesum;  // exclusive prefix over lanes
    int bucket = -1, nk = 0;
    #pragma unroll
    for (int i = 0; i < 8; i++) {
        if (bucket < 0 && (unsigned)kk >= run && (unsigned)kk < run + cc[i]) {
            bucket = lane * 8 + i;
            nk = kk - (int)run;
        }
        run += cc[i];
    }
    unsigned bal = __ballot_sync(0xffffffffu, bucket >= 0);
    int srcl = __ffs(bal) - 1;
    int bb = __shfl_sync(0xffffffffu, bucket, srcl);
    kk = __shfl_sync(0xffffffffu, nk, srcl);
    return (unsigned)bb;
}

__global__ void __launch_bounds__(NTHREADS, 4)
select_kernel(const float* __restrict__ xf, const float* __restrict__ xr) {
    extern __shared__ unsigned smem[];
    unsigned*       seg  = smem;                              // [G][CAPC]
    unsigned*       scnt = smem + G * CAPC;                   // [G]
    unsigned short* hist = (unsigned short*)(smem + G * CAPC + G);  // [NWARP][256] u16

    const int tid  = threadIdx.x;
    const int lane = tid & 31;
    const int w    = tid >> 5;

    const int bid    = blockIdx.x;               // 2048 blocks
    const int tensor = bid >> 10;
    const int rem    = bid & 1023;
    const int t      = rem >> 2;
    const int dgrp   = rem & 3;                  // which group of 16 columns

    const float* src = tensor ? xr : xf;
    const int c = tid & 3;                       // this thread's float4-column (0..3)
    const float4* p = reinterpret_cast<const float4*>(src) + (t * 16 + dgrp * 4 + c);
    const float THR = -1.45f;

    if (tid < G) scnt[tid] = 0;
    __syncthreads();

    // ---- software-pipelined streaming load + sparse atomic capture ----
    // Double-buffered prefetch: batch i+4 is issued BEFORE batch i is
    // processed, so each warp always has >=4 loads in flight during the
    // capture work (R8's serial load->process loop exposed the full
    // queue-inflated DRAM latency every 4 rows).
    float4 bufA[4], bufB[4];
    #pragma unroll
    for (int u = 0; u < 4; u++) {
        int r = u * 64 + (tid >> 2);
        bufA[u] = __ldg(p + (size_t)r * (NCOL / 4));
    }

    #pragma unroll 1
    for (int it = 0; it < 64; it += 8) {
        // prefetch batch it+4
        #pragma unroll
        for (int u = 0; u < 4; u++) {
            int r = (it + 4 + u) * 64 + (tid >> 2);
            bufB[u] = __ldg(p + (size_t)r * (NCOL / 4));
        }
        // process batch it (bufA)
        #pragma unroll
        for (int u = 0; u < 4; u++) {
            float vv[4] = {bufA[u].x, bufA[u].y, bufA[u].z, bufA[u].w};
            #pragma unroll
            for (int jj = 0; jj < 4; jj++) {
                float v = vv[jj];
                if (v < THR) {
                    int col = c * 4 + jj;
                    unsigned slot = atomicAdd(&scnt[col], 1u);
                    if (slot < CAPC) seg[col * CAPC + slot] = ~__float_as_uint(v);
                }
            }
        }
        // prefetch batch it+8 (skip past the end)
        if (it + 8 < 64) {
            #pragma unroll
            for (int u = 0; u < 4; u++) {
                int r = (it + 8 + u) * 64 + (tid >> 2);
                bufA[u] = __ldg(p + (size_t)r * (NCOL / 4));
            }
        }
        // process batch it+4 (bufB)
        #pragma unroll
        for (int u = 0; u < 4; u++) {
            float vv[4] = {bufB[u].x, bufB[u].y, bufB[u].z, bufB[u].w};
            #pragma unroll
            for (int jj = 0; jj < 4; jj++) {
                float v = vv[jj];
                if (v < THR) {
                    int col = c * 4 + jj;
                    unsigned slot = atomicAdd(&scnt[col], 1u);
                    if (slot < CAPC) seg[col * CAPC + slot] = ~__float_as_uint(v);
                }
            }
        }
    }
    __syncthreads();

    // ---- select: warp w owns columns w and w+8, flat candidate arrays ----
    unsigned short* h   = hist + w * 256;
    unsigned*       h32 = (unsigned*)h;          // for zeroing (128 words)
    const unsigned  lmlt = (1u << lane) - 1u;

    for (int cc2 = 0; cc2 < 2; cc2++) {
        const int col = w + cc2 * NWARP;
        unsigned* colb = seg + col * CAPC;
        const int cnt0 = (int)scnt[col];

        unsigned prefix = 0;
        int k = KRANK;

        if (cnt0 > KRANK && cnt0 <= CAPC) {
            int cntf = cnt0;
            for (int shift = 24; shift >= 0; shift -= 8) {
                #pragma unroll
                for (int i = 0; i < 4; i++) h32[i * 32 + lane] = 0;
                __syncwarp();
                for (int i0 = 0; i0 < cntf; i0 += 32) {
                    int i = i0 + lane;
                    bool a = i < cntf;
                    unsigned key = a ? colb[i] : 0u;
                    unsigned m = __ballot_sync(0xffffffffu, a);
                    if (a) {
                        unsigned bin = (key >> shift) & 255u;
                        unsigned peers = __match_any_sync(m, bin);
                        if (lane == __ffs(peers) - 1)
                            h[bin] = (unsigned short)(h[bin] + __popc(peers));
                    }
                }
                __syncwarp();
                unsigned c8[8];
                #pragma unroll
                for (int i = 0; i < 8; i++) c8[i] = h[lane * 8 + i];
                unsigned bucket = find_bucket(c8, k, lane);
                prefix |= bucket << shift;
                if (shift > 0) {
                    // in-place compaction; writes never pass the read frontier
                    int np = 0;
                    for (int i0 = 0; i0 < cntf; i0 += 32) {
                        int i = i0 + lane;
                        bool a = i < cntf;
                        unsigned key = a ? colb[i] : 0u;
                        bool ok = a && (((key >> shift) & 255u) == bucket);
                        unsigned m = __ballot_sync(0xffffffffu, ok);
                        if (ok) colb[np + __popc(m & lmlt)] = key;
                        np += __popc(m);
                    }
                    cntf = np;
                }
            }
        } else {
            // exact fallback (astronomically rare): 4-pass radix re-reading global
            const int cglob = t * 64 + dgrp * 16 + col;
            for (int shift = 24; shift >= 0; shift -= 8) {
                #pragma unroll
                for (int i = 0; i < 4; i++) h32[i * 32 + lane] = 0;
                __syncwarp();
                for (int i = lane; i < NB; i += 32) {
                    unsigned key = key_of(__ldg(src + (size_t)i * NCOL + cglob));
                    bool act = (shift == 24) ||
                               ((key >> (shift + 8)) == (prefix >> (shift + 8)));
                    unsigned m = __ballot_sync(0xffffffffu, act);
                    if (act) {
                        unsigned bin = (key >> shift) & 255u;
                        unsigned peers = __match_any_sync(m, bin);
                        if (lane == __ffs(peers) - 1)
                            h[bin] = (unsigned short)(h[bin] + __popc(peers));
                    }
                }
                __syncwarp();
                unsigned c8[8];
                #pragma unroll
                for (int i = 0; i < 8; i++) c8[i] = h[lane * 8 + i];
                unsigned bucket = find_bucket(c8, k, lane);
                prefix |= bucket << shift;
            }
        }

        if (lane == 0)
            g_var[tensor * NCOL + t * ND + dgrp * G + col] = float_of(prefix);
    }
}

// 16 blocks x 1024 threads: deterministic partial sums into fixed slots
__global__ void reduce_part(void) {
    const int tid  = threadIdx.x;
    const int lane = tid & 31;
    const int wid  = tid >> 5;
    const int i    = blockIdx.x * 1024 + tid;

    float vf = g_var[i];
    float vr = g_var[NCOL + i];
    float d  = fabsf(vf - vr);
    double a = (double)d;
    double r = (double)(d / (fabsf(vr) + 1e-8f));

    #pragma unroll
    for (int off = 16; off > 0; off >>= 1) {
        a += __shfl_down_sync(0xffffffffu, a, off);
        r += __shfl_down_sync(0xffffffffu, r, off);
    }
    __shared__ double sa[32], sr[32];
    if (lane == 0) { sa[wid] = a; sr[wid] = r; }
    __syncthreads();
    if (tid < 32) {
        a = sa[tid]; r = sr[tid];
        #pragma unroll
        for (int off = 16; off > 0; off >>= 1) {
            a += __shfl_down_sync(0xffffffffu, a, off);
            r += __shfl_down_sync(0xffffffffu, r, off);
        }
        if (tid == 0) { g_pa[blockIdx.x] = a; g_pr[blockIdx.x] = r; }
    }
}

// single thread: fixed-order final sum -> bitwise deterministic
__global__ void finalize_kernel(float* __restrict__ out) {
    double a = 0.0, r = 0.0;
    #pragma unroll
    for (int i = 0; i < 16; i++) { a += g_pa[i]; r += g_pr[i]; }
    out[0] = (float)(a / (double)NCOL);
    out[1] = (float)(r / (double)NCOL);
}

extern "C" void kernel_launch(void* const* d_in, const int* in_sizes, int n_in,
                              void* d_out, int out_size) {
    const float* xf = (const float*)d_in[0];
    const float* xr = (const float*)d_in[1];
    const int smem_bytes = (G * CAPC + G) * 4 + NWARP * 256 * 2;  // 30784
    cudaFuncSetAttribute(select_kernel,
                         cudaFuncAttributeMaxDynamicSharedMemorySize, smem_bytes);
    select_kernel<<<2 * NT * (ND / G), NTHREADS, smem_bytes>>>(xf, xr);
    reduce_part<<<16, 1024>>>();
    finalize_kernel<<<1, 1>>>((float*)d_out);
}